// round 9
// baseline (speedup 1.0000x reference)
#include <cuda_runtime.h>

// Problem constants
#define NB   32
#define NCH  3
#define HH   128
#define RR   127                 // output spatial size = H - K + 1
#define NLOC (NB*RR*RR)

// Circuit matrix U (16x16, row-major): state' = U * s
__device__ float g_U[256];

// ---------------------------------------------------------------------------
// Prep kernel (separate launch: keeps its huge register footprint out of the
// main kernel's allocation — fused variants cost 128-255 regs).
// Thread j evolves basis column j through the 4-layer circuit.
// ---------------------------------------------------------------------------
__global__ void prep_kernel(const float* __restrict__ w) {
    int j = threadIdx.x;
    if (j >= 16) return;
    float m[16];
#pragma unroll
    for (int i = 0; i < 16; i++) m[i] = (i == j) ? 1.0f : 0.0f;

    for (int layer = 0; layer < 4; layer++) {
#pragma unroll
        for (int q = 0; q < 4; q++) {
            float t = 0.5f * w[layer * 4 + q];
            float c = cosf(t), s = sinf(t);
            int mask = 8 >> q;
#pragma unroll
            for (int i0 = 0; i0 < 16; i0++) {
                if (i0 & mask) continue;
                int i1 = i0 | mask;
                float a0 = m[i0], a1 = m[i1];
                m[i0] = c * a0 - s * a1;
                m[i1] = s * a0 + c * a1;
            }
        }
        // CNOT(0,1): ctrl bit 8, tgt bit 4
#pragma unroll
        for (int i = 0; i < 16; i++)
            if ((i & 8) && !(i & 4)) { float tt = m[i]; m[i] = m[i | 4]; m[i | 4] = tt; }
        // CNOT(2,3): ctrl bit 2, tgt bit 1
#pragma unroll
        for (int i = 0; i < 16; i++)
            if ((i & 2) && !(i & 1)) { float tt = m[i]; m[i] = m[i | 1]; m[i | 1] = tt; }
        // CNOT(1,2): ctrl bit 4, tgt bit 2
#pragma unroll
        for (int i = 0; i < 16; i++)
            if ((i & 4) && !(i & 2)) { float tt = m[i]; m[i] = m[i | 2]; m[i | 2] = tt; }
    }
#pragma unroll
    for (int i = 0; i < 16; i++) g_U[i * 16 + j] = m[i];
}

// ---------------------------------------------------------------------------
// Main kernel: one thread per output location.
// Channel-outer loop (NOT unrolled) keeps live set to one channel:
//   persistent = s[16] + P[16] = 32 regs (+ ~25 transients).
// launch_bounds(256,3) -> 85-reg ceiling, 3 blocks/SM (24 warps, occ ~34%)
// vs R1's 87 regs / 2 blocks / 22.6%.
// ---------------------------------------------------------------------------
__global__ void __launch_bounds__(256, 3) rqcnn_main(const float* __restrict__ x,
                                                     float* __restrict__ out) {
    __shared__ __align__(16) float sU[256];
    sU[threadIdx.x] = g_U[threadIdx.x];
    __syncthreads();

    int gid = blockIdx.x * 256 + threadIdx.x;
    if (gid >= NLOC) return;

    int j  = gid % RR;
    int t2 = gid / RR;
    int i  = t2 % RR;
    int b  = t2 / RR;

    const float HPI = 1.57079632679489662f;  // pi/2

    float P[16];
#pragma unroll
    for (int r = 0; r < 16; r++) P[r] = 0.0f;

    const float* px = x + (((b * NCH) * HH) + i) * HH + j;

#pragma unroll 1
    for (int c = 0; c < NCH; c++) {
        // scalar 4B loads: patch base is only 4B-aligned for odd j
        float p00 = px[0];
        float p01 = px[1];
        float p10 = px[HH];
        float p11 = px[HH + 1];
        px += HH * HH;

        float ca, sa, cb, sb, cc, sc, cd, sd;
        __sincosf(p00 * HPI, &sa, &ca);   // qubit a: (i,   j)
        __sincosf(p01 * HPI, &sb, &cb);   // qubit b: (i,   j+1)
        __sincosf(p10 * HPI, &sc, &cc);   // qubit c: (i+1, j)
        __sincosf(p11 * HPI, &sd, &cd);   // qubit d: (i+1, j+1)

        float ab00 = ca * cb, ab01 = ca * sb, ab10 = sa * cb, ab11 = sa * sb;
        float cd00 = cc * cd, cd01 = cc * sd, cd10 = sc * cd, cd11 = sc * sd;

        float s[16];
        s[0]  = ab00 * cd00; s[1]  = ab00 * cd01; s[2]  = ab00 * cd10; s[3]  = ab00 * cd11;
        s[4]  = ab01 * cd00; s[5]  = ab01 * cd01; s[6]  = ab01 * cd10; s[7]  = ab01 * cd11;
        s[8]  = ab10 * cd00; s[9]  = ab10 * cd01; s[10] = ab10 * cd10; s[11] = ab10 * cd11;
        s[12] = ab11 * cd00; s[13] = ab11 * cd01; s[14] = ab11 * cd10; s[15] = ab11 * cd11;

#pragma unroll
        for (int r = 0; r < 16; r++) {
            const float4* row = reinterpret_cast<const float4*>(sU + r * 16);
            float4 u0 = row[0], u1 = row[1], u2 = row[2], u3 = row[3];
            float y;
            y = u0.x * s[0];
            y = fmaf(u0.y, s[1],  y);
            y = fmaf(u0.z, s[2],  y);
            y = fmaf(u0.w, s[3],  y);
            y = fmaf(u1.x, s[4],  y);
            y = fmaf(u1.y, s[5],  y);
            y = fmaf(u1.z, s[6],  y);
            y = fmaf(u1.w, s[7],  y);
            y = fmaf(u2.x, s[8],  y);
            y = fmaf(u2.y, s[9],  y);
            y = fmaf(u2.z, s[10], y);
            y = fmaf(u2.w, s[11], y);
            y = fmaf(u3.x, s[12], y);
            y = fmaf(u3.y, s[13], y);
            y = fmaf(u3.z, s[14], y);
            y = fmaf(u3.w, s[15], y);
            P[r] = fmaf(y, y, P[r]);
        }
    }

    // Signed butterfly: z_q = sum_r sgn(bit_{3-q}(r)) * P_r
    float z3 = (P[0] - P[1]) + (P[2] - P[3]) + (P[4] - P[5]) + (P[6] - P[7])
             + (P[8] - P[9]) + (P[10] - P[11]) + (P[12] - P[13]) + (P[14] - P[15]);
    float e0 = P[0]  + P[1],  e1 = P[2]  + P[3],  e2 = P[4]  + P[5],  e3 = P[6]  + P[7];
    float e4 = P[8]  + P[9],  e5 = P[10] + P[11], e6 = P[12] + P[13], e7 = P[14] + P[15];
    float z2 = (e0 - e1) + (e2 - e3) + (e4 - e5) + (e6 - e7);
    float f0 = e0 + e1, f1 = e2 + e3, f2 = e4 + e5, f3 = e6 + e7;
    float z1 = (f0 - f1) + (f2 - f3);
    float z0 = (f0 + f1) - (f2 + f3);

    // Output: q_out[B,R,R,DEPTH] contiguous (memory reinterpret of [B,DEPTH,R,R])
    reinterpret_cast<float4*>(out)[gid] = make_float4(z0, z1, z2, z3);
}

extern "C" void kernel_launch(void* const* d_in, const int* in_sizes, int n_in,
                              void* d_out, int out_size) {
    const float* x = (const float*)d_in[0];   // [32,3,128,128] float32
    const float* w = (const float*)d_in[1];   // [4,4] float32
    float* out = (float*)d_out;               // [32,4,127,127] float32

    prep_kernel<<<1, 16>>>(w);
    int blocks = (NLOC + 255) / 256;
    rqcnn_main<<<blocks, 256>>>(x, out);
}

// round 10
// speedup vs baseline: 4.0046x; 4.0046x over previous
#include <cuda_runtime.h>

// Problem constants
#define NB   32
#define NCH  3
#define HH   128
#define RR   127      // output spatial size = H - K + 1
#define NLOC (NB*RR*RR)
#define TPB  128      // 128-thread blocks -> ~5 blocks/SM at ~90 regs (vs 2 at 256)

// ---------------------------------------------------------------------------
// Single fused kernel, R1's exact proven hot path (87 regs, no spill).
// Threads 0-15 of each block build the 16x16 circuit matrix U in shared
// memory using __sincosf (MUFU-only: no slow-path code, so the prep branch
// stays register-cheap, unlike cosf/sinf which blew the allocation to 255).
// Then each thread computes ONE output location:
//   s[3][16] product states (channels fully unrolled - the only shape that
//   ptxas allocates cleanly), y_r = U_r . s_c, P_r = sum_c y^2,
//   z = signed butterfly, float4 store.
// ---------------------------------------------------------------------------
__global__ void rqcnn_main(const float* __restrict__ x,
                           const float* __restrict__ w,
                           float* __restrict__ out) {
    __shared__ __align__(16) float sU[256];

    if (threadIdx.x < 16) {
        int jj = threadIdx.x;
        float m[16];
#pragma unroll
        for (int i = 0; i < 16; i++) m[i] = (i == jj) ? 1.0f : 0.0f;
        for (int layer = 0; layer < 4; layer++) {
#pragma unroll
            for (int q = 0; q < 4; q++) {
                float t = 0.5f * w[layer * 4 + q];
                float c, s;
                __sincosf(t, &s, &c);          // |t| <= pi: MUFU fast path only
                int mask = 8 >> q;
#pragma unroll
                for (int i0 = 0; i0 < 16; i0++) {
                    if (i0 & mask) continue;
                    int i1 = i0 | mask;
                    float a0 = m[i0], a1 = m[i1];
                    m[i0] = c * a0 - s * a1;
                    m[i1] = s * a0 + c * a1;
                }
            }
            // CNOT(0,1): ctrl bit 8, tgt bit 4
#pragma unroll
            for (int i = 0; i < 16; i++)
                if ((i & 8) && !(i & 4)) { float tt = m[i]; m[i] = m[i | 4]; m[i | 4] = tt; }
            // CNOT(2,3): ctrl bit 2, tgt bit 1
#pragma unroll
            for (int i = 0; i < 16; i++)
                if ((i & 2) && !(i & 1)) { float tt = m[i]; m[i] = m[i | 1]; m[i | 1] = tt; }
            // CNOT(1,2): ctrl bit 4, tgt bit 2
#pragma unroll
            for (int i = 0; i < 16; i++)
                if ((i & 4) && !(i & 2)) { float tt = m[i]; m[i] = m[i | 2]; m[i | 2] = tt; }
        }
#pragma unroll
        for (int i = 0; i < 16; i++) sU[i * 16 + jj] = m[i];
    }
    __syncthreads();

    int gid = blockIdx.x * TPB + threadIdx.x;
    if (gid >= NLOC) return;

    int j  = gid % RR;
    int t2 = gid / RR;
    int i  = t2 % RR;
    int b  = t2 / RR;

    const float HPI = 1.57079632679489662f;  // pi/2

    float s[NCH][16];
#pragma unroll
    for (int c = 0; c < NCH; c++) {
        const float* px = x + (((b * NCH + c) * HH) + i) * HH + j;
        float p00 = px[0], p01 = px[1], p10 = px[HH], p11 = px[HH + 1];
        float ca, sa, cb, sb, cc, sc, cd, sd;
        __sincosf(p00 * HPI, &sa, &ca);   // qubit a: (i,   j)
        __sincosf(p01 * HPI, &sb, &cb);   // qubit b: (i,   j+1)
        __sincosf(p10 * HPI, &sc, &cc);   // qubit c: (i+1, j)
        __sincosf(p11 * HPI, &sd, &cd);   // qubit d: (i+1, j+1)

        float ab00 = ca * cb, ab01 = ca * sb, ab10 = sa * cb, ab11 = sa * sb;
        float cd00 = cc * cd, cd01 = cc * sd, cd10 = sc * cd, cd11 = sc * sd;

        s[c][0]  = ab00 * cd00; s[c][1]  = ab00 * cd01; s[c][2]  = ab00 * cd10; s[c][3]  = ab00 * cd11;
        s[c][4]  = ab01 * cd00; s[c][5]  = ab01 * cd01; s[c][6]  = ab01 * cd10; s[c][7]  = ab01 * cd11;
        s[c][8]  = ab10 * cd00; s[c][9]  = ab10 * cd01; s[c][10] = ab10 * cd10; s[c][11] = ab10 * cd11;
        s[c][12] = ab11 * cd00; s[c][13] = ab11 * cd01; s[c][14] = ab11 * cd10; s[c][15] = ab11 * cd11;
    }

    float P[16];
#pragma unroll
    for (int r = 0; r < 16; r++) {
        const float4* row = reinterpret_cast<const float4*>(sU + r * 16);
        float4 u0 = row[0], u1 = row[1], u2 = row[2], u3 = row[3];
        float acc = 0.0f;
#pragma unroll
        for (int c = 0; c < NCH; c++) {
            float y;
            y = u0.x * s[c][0];
            y = fmaf(u0.y, s[c][1],  y);
            y = fmaf(u0.z, s[c][2],  y);
            y = fmaf(u0.w, s[c][3],  y);
            y = fmaf(u1.x, s[c][4],  y);
            y = fmaf(u1.y, s[c][5],  y);
            y = fmaf(u1.z, s[c][6],  y);
            y = fmaf(u1.w, s[c][7],  y);
            y = fmaf(u2.x, s[c][8],  y);
            y = fmaf(u2.y, s[c][9],  y);
            y = fmaf(u2.z, s[c][10], y);
            y = fmaf(u2.w, s[c][11], y);
            y = fmaf(u3.x, s[c][12], y);
            y = fmaf(u3.y, s[c][13], y);
            y = fmaf(u3.z, s[c][14], y);
            y = fmaf(u3.w, s[c][15], y);
            acc = fmaf(y, y, acc);
        }
        P[r] = acc;
    }

    // Signed butterfly: z_q = sum_r sgn(bit_{3-q}(r)) * P_r
    float z3 = (P[0] - P[1]) + (P[2] - P[3]) + (P[4] - P[5]) + (P[6] - P[7])
             + (P[8] - P[9]) + (P[10] - P[11]) + (P[12] - P[13]) + (P[14] - P[15]);
    float e0 = P[0]  + P[1],  e1 = P[2]  + P[3],  e2 = P[4]  + P[5],  e3 = P[6]  + P[7];
    float e4 = P[8]  + P[9],  e5 = P[10] + P[11], e6 = P[12] + P[13], e7 = P[14] + P[15];
    float z2 = (e0 - e1) + (e2 - e3) + (e4 - e5) + (e6 - e7);
    float f0 = e0 + e1, f1 = e2 + e3, f2 = e4 + e5, f3 = e6 + e7;
    float z1 = (f0 - f1) + (f2 - f3);
    float z0 = (f0 + f1) - (f2 + f3);

    // Output: q_out[B,R,R,DEPTH] contiguous (memory reinterpret of [B,DEPTH,R,R])
    reinterpret_cast<float4*>(out)[gid] = make_float4(z0, z1, z2, z3);
}

extern "C" void kernel_launch(void* const* d_in, const int* in_sizes, int n_in,
                              void* d_out, int out_size) {
    const float* x = (const float*)d_in[0];   // [32,3,128,128] float32
    const float* w = (const float*)d_in[1];   // [4,4] float32
    float* out = (float*)d_out;               // [32,4,127,127] float32

    int blocks = (NLOC + TPB - 1) / TPB;
    rqcnn_main<<<blocks, TPB>>>(x, w, out);
}